// round 1
// baseline (speedup 1.0000x reference)
#include <cuda_runtime.h>
#include <cstdint>

typedef unsigned long long ull;

// ---------------- packed f32x2 helpers (Blackwell) ----------------
__device__ __forceinline__ ull pack2(float lo, float hi) {
    ull r;
    asm("mov.b64 %0, {%1, %2};" : "=l"(r) : "f"(lo), "f"(hi));
    return r;
}
__device__ __forceinline__ void unpack2(ull v, float& lo, float& hi) {
    asm("mov.b64 {%0, %1}, %2;" : "=f"(lo), "=f"(hi) : "l"(v));
}
__device__ __forceinline__ void fma2(ull& d, ull a, ull b) {
    asm("fma.rn.f32x2 %0, %1, %2, %0;" : "+l"(d) : "l"(a), "l"(b));
}

// ---------------- problem constants ----------------
// X: [32,128,128,64], A: [32,128,128], W: [64,64], b: [64]
static constexpr int NB = 32;
static constexpr int NN = 128;
static constexpr int DD = 64;

// smem layout (floats). Padded stride 132 for [dim][k] transposed arrays.
static constexpr int TS = 132;                 // transposed/A row stride
static constexpr int OFF_XT  = 0;              // Xt [64][132] = 8448 floats; later h2 [128][64] = 8192
static constexpr int OFF_H1T = 8448;           // h1t [64][132] = 8448 floats
static constexpr int OFF_W1  = 16896;          // 4096
static constexpr int OFF_W2  = 20992;          // 4096
static constexpr int OFF_A   = 8448;           // A [128][132] = 16896 (overlays h1t+W1+W2 after layer 2)
static constexpr int SMEM_FLOATS = 25344;      // = 8448 + 16896
static constexpr int SMEM_BYTES  = SMEM_FLOATS * 4;   // 101376

__global__ __launch_bounds__(256, 2)
void crosssubg_fused_kernel(const float* __restrict__ X,
                            const float* __restrict__ A,
                            const float* __restrict__ W1,
                            const float* __restrict__ b1,
                            const float* __restrict__ W2,
                            const float* __restrict__ b2,
                            float* __restrict__ out)
{
    extern __shared__ float sm[];

    const int i = blockIdx.x;          // 0..127
    const int b = blockIdx.y;          // 0..31
    const int tid = (int)threadIdx.x;  // 0..255
    const int dg  = tid & 7;           // column group (8 outputs)
    const int kg  = tid >> 3;          // row group (4 rows), 0..31
    const int c0  = dg * 8;            // output-col base (e or d or d)
    const int r0  = kg * 4;            // row base (k or k or j)

    const size_t tile = (size_t)(b * NN + i);
    const float* gX = X + tile * (NN * DD);

    // ---------- Phase 0: stage X (transposed) + W1 + W2 ----------
    {
        const float4* gX4 = (const float4*)gX;     // 2048 float4
        #pragma unroll
        for (int it = 0; it < 8; ++it) {
            int t = tid + it * 256;                // t < 2048
            int k = t >> 4, dq = t & 15;           // d = 4*dq + c
            float4 v = gX4[t];
            float* p = &sm[OFF_XT + (dq * 4) * TS + k];
            p[0]      = v.x;
            p[TS]     = v.y;
            p[2 * TS] = v.z;
            p[3 * TS] = v.w;
        }
        const float4* gW1 = (const float4*)W1;
        const float4* gW2 = (const float4*)W2;
        float4* sW1 = (float4*)&sm[OFF_W1];
        float4* sW2 = (float4*)&sm[OFF_W2];
        #pragma unroll
        for (int it = 0; it < 4; ++it) {
            int t = tid + it * 256;                // t < 1024
            sW1[t] = gW1[t];
            sW2[t] = gW2[t];
        }
    }
    __syncthreads();

    // ---------- Phase 1: layer 1  h1[k][e] = relu(b1[e] + sum_d X[k][d] W1[d][e]) ----------
    ull acc[4][4];
    {
        #pragma unroll
        for (int p = 0; p < 4; ++p) {
            float lo = __ldg(&b1[c0 + 2 * p]);
            float hi = __ldg(&b1[c0 + 2 * p + 1]);
            ull v = pack2(lo, hi);
            acc[0][p] = v; acc[1][p] = v; acc[2][p] = v; acc[3][p] = v;
        }
        #pragma unroll 4
        for (int d = 0; d < DD; ++d) {
            float4 xv = *(const float4*)&sm[OFF_XT + d * TS + r0];
            ulonglong2 w01 = *(const ulonglong2*)&sm[OFF_W1 + d * DD + c0];
            ulonglong2 w23 = *(const ulonglong2*)&sm[OFF_W1 + d * DD + c0 + 4];
            ull wp0 = w01.x, wp1 = w01.y, wp2 = w23.x, wp3 = w23.y;
            float xs[4] = {xv.x, xv.y, xv.z, xv.w};
            #pragma unroll
            for (int kk = 0; kk < 4; ++kk) {
                ull xa = pack2(xs[kk], xs[kk]);
                fma2(acc[kk][0], xa, wp0);
                fma2(acc[kk][1], xa, wp1);
                fma2(acc[kk][2], xa, wp2);
                fma2(acc[kk][3], xa, wp3);
            }
        }
        // relu + store transposed h1t[e][k]
        float r[4][8];
        #pragma unroll
        for (int kk = 0; kk < 4; ++kk)
            #pragma unroll
            for (int p = 0; p < 4; ++p) {
                float lo, hi;
                unpack2(acc[kk][p], lo, hi);
                r[kk][2 * p]     = fmaxf(lo, 0.f);
                r[kk][2 * p + 1] = fmaxf(hi, 0.f);
            }
        #pragma unroll
        for (int ee = 0; ee < 8; ++ee) {
            float4 v = make_float4(r[0][ee], r[1][ee], r[2][ee], r[3][ee]);
            *(float4*)&sm[OFF_H1T + (c0 + ee) * TS + r0] = v;
        }
    }
    __syncthreads();   // all Xt reads + h1t writes done

    // ---------- Phase 2: layer 2  h2[k][d] = relu(b2[d] + sum_e h1[k][e] W2[e][d]) ----------
    {
        #pragma unroll
        for (int p = 0; p < 4; ++p) {
            float lo = __ldg(&b2[c0 + 2 * p]);
            float hi = __ldg(&b2[c0 + 2 * p + 1]);
            ull v = pack2(lo, hi);
            acc[0][p] = v; acc[1][p] = v; acc[2][p] = v; acc[3][p] = v;
        }
        #pragma unroll 4
        for (int e = 0; e < DD; ++e) {
            float4 xv = *(const float4*)&sm[OFF_H1T + e * TS + r0];
            ulonglong2 w01 = *(const ulonglong2*)&sm[OFF_W2 + e * DD + c0];
            ulonglong2 w23 = *(const ulonglong2*)&sm[OFF_W2 + e * DD + c0 + 4];
            ull wp0 = w01.x, wp1 = w01.y, wp2 = w23.x, wp3 = w23.y;
            float xs[4] = {xv.x, xv.y, xv.z, xv.w};
            #pragma unroll
            for (int kk = 0; kk < 4; ++kk) {
                ull xa = pack2(xs[kk], xs[kk]);
                fma2(acc[kk][0], xa, wp0);
                fma2(acc[kk][1], xa, wp1);
                fma2(acc[kk][2], xa, wp2);
                fma2(acc[kk][3], xa, wp3);
            }
        }
        // relu + store natural h2[k][d] into OFF_XT region (Xt is dead)
        #pragma unroll
        for (int kk = 0; kk < 4; ++kk) {
            float v[8];
            #pragma unroll
            for (int p = 0; p < 4; ++p) {
                float lo, hi;
                unpack2(acc[kk][p], lo, hi);
                v[2 * p]     = fmaxf(lo, 0.f);
                v[2 * p + 1] = fmaxf(hi, 0.f);
            }
            *(float4*)&sm[OFF_XT + (r0 + kk) * DD + c0]     = make_float4(v[0], v[1], v[2], v[3]);
            *(float4*)&sm[OFF_XT + (r0 + kk) * DD + c0 + 4] = make_float4(v[4], v[5], v[6], v[7]);
        }
    }
    __syncthreads();   // h1t/W reads done -> safe to overlay A; h2 complete

    // ---------- Phase 3: stage A[b] ([k][j], padded stride) ----------
    {
        const float4* gA4 = (const float4*)(A + (size_t)b * NN * NN);  // 4096 float4
        #pragma unroll
        for (int it = 0; it < 16; ++it) {
            int t = tid + it * 256;                 // t < 4096
            int k = t >> 5, jq = t & 31;
            *(float4*)&sm[OFF_A + k * TS + jq * 4] = gA4[t];
        }
    }
    __syncthreads();

    // ---------- Phase 4: aggregation  out[j][d] = sum_k A[k][j] * h2[k][d] ----------
    {
        ull o[4][4];
        #pragma unroll
        for (int jj = 0; jj < 4; ++jj)
            #pragma unroll
            for (int p = 0; p < 4; ++p) o[jj][p] = 0ull;

        #pragma unroll 2
        for (int k = 0; k < NN; ++k) {
            float4 av = *(const float4*)&sm[OFF_A + k * TS + r0];       // A[k][j0..j0+3]
            ulonglong2 h01 = *(const ulonglong2*)&sm[OFF_XT + k * DD + c0];
            ulonglong2 h23 = *(const ulonglong2*)&sm[OFF_XT + k * DD + c0 + 4];
            ull hp0 = h01.x, hp1 = h01.y, hp2 = h23.x, hp3 = h23.y;
            float as[4] = {av.x, av.y, av.z, av.w};
            #pragma unroll
            for (int jj = 0; jj < 4; ++jj) {
                ull ap = pack2(as[jj], as[jj]);
                fma2(o[jj][0], ap, hp0);
                fma2(o[jj][1], ap, hp1);
                fma2(o[jj][2], ap, hp2);
                fma2(o[jj][3], ap, hp3);
            }
        }

        float* gO = out + tile * (NN * DD);
        #pragma unroll
        for (int jj = 0; jj < 4; ++jj) {
            ulonglong2 v0; v0.x = o[jj][0]; v0.y = o[jj][1];
            ulonglong2 v1; v1.x = o[jj][2]; v1.y = o[jj][3];
            *(ulonglong2*)&gO[(r0 + jj) * DD + c0]     = v0;
            *(ulonglong2*)&gO[(r0 + jj) * DD + c0 + 4] = v1;
        }
    }
}

extern "C" void kernel_launch(void* const* d_in, const int* in_sizes, int n_in,
                              void* d_out, int out_size)
{
    // Defensive input mapping by size (order-preserving for equal sizes).
    const float *X = nullptr, *A = nullptr, *W1 = nullptr, *b1 = nullptr,
                *W2 = nullptr, *b2 = nullptr;
    for (int idx = 0; idx < n_in; ++idx) {
        const float* p = (const float*)d_in[idx];
        int s = in_sizes[idx];
        if      (s == NB * NN * NN * DD) X = p;
        else if (s == NB * NN * NN)      A = p;
        else if (s == DD * DD)           { if (!W1) W1 = p; else W2 = p; }
        else if (s == DD)                { if (!b1) b1 = p; else b2 = p; }
    }

    cudaFuncSetAttribute(crosssubg_fused_kernel,
                         cudaFuncAttributeMaxDynamicSharedMemorySize, SMEM_BYTES);

    dim3 grid(NN, NB);   // (i, b) -> 4096 CTAs
    crosssubg_fused_kernel<<<grid, 256, SMEM_BYTES>>>(X, A, W1, b1, W2, b2,
                                                      (float*)d_out);
}

// round 3
// speedup vs baseline: 3.0916x; 3.0916x over previous
#include <cuda_runtime.h>
#include <cuda_bf16.h>
#include <cstdint>

typedef uint32_t u32;
typedef uint64_t u64;

static constexpr int NB = 32, NN = 128, DD = 64;

// Precomputed A-transpose bf16 hi/lo images: At[j][k] = A[b][k][j],
// rows j=0..127, row stride 136 bf16 (272B), 128 valid k + pad.
__device__ __align__(16) unsigned char g_Aimg[32][2][34816];

// ---------------- helpers ----------------
__device__ __forceinline__ u32 smem_u32(const void* p) {
    u32 a;
    asm("{ .reg .u64 t; cvta.to.shared.u64 t, %1; cvt.u32.u64 %0, t; }" : "=r"(a) : "l"(p));
    return a;
}
__device__ __forceinline__ u32 pack_bf(float lo, float hi) {
    u32 r;  // result = {hi16 = cvt(hi), lo16 = cvt(lo)}
    asm("cvt.rn.bf16x2.f32 %0, %1, %2;" : "=r"(r) : "f"(hi), "f"(lo));
    return r;
}
__device__ __forceinline__ float bf_round(float v) {
    __nv_bfloat16 h = __float2bfloat16(v);
    return __bfloat162float(h);
}
__device__ __forceinline__ unsigned short bf16bits(float v) {
    __nv_bfloat16 h = __float2bfloat16(v);
    return *reinterpret_cast<unsigned short*>(&h);
}
__device__ __forceinline__ void sts16(u32 a, unsigned short v) {
    asm volatile("st.shared.u16 [%0], %1;" :: "r"(a), "h"(v) : "memory");
}
__device__ __forceinline__ void sts32(u32 a, u32 v) {
    asm volatile("st.shared.b32 [%0], %1;" :: "r"(a), "r"(v) : "memory");
}
__device__ __forceinline__ void sts64(u32 a, u32 x, u32 y) {
    asm volatile("st.shared.v2.b32 [%0], {%1,%2};" :: "r"(a), "r"(x), "r"(y) : "memory");
}
__device__ __forceinline__ void sts128(u32 a, u32 x, u32 y, u32 z, u32 w) {
    asm volatile("st.shared.v4.b32 [%0], {%1,%2,%3,%4};" :: "r"(a), "r"(x), "r"(y), "r"(z), "r"(w) : "memory");
}
__device__ __forceinline__ void lds64f(float& x, float& y, u32 a) {
    asm volatile("ld.shared.v2.f32 {%0,%1}, [%2];" : "=f"(x), "=f"(y) : "r"(a));
}
__device__ __forceinline__ void ldsm4(u32* f, u32 a) {
    asm volatile("ldmatrix.sync.aligned.m8n8.x4.shared.b16 {%0,%1,%2,%3}, [%4];"
                 : "=r"(f[0]), "=r"(f[1]), "=r"(f[2]), "=r"(f[3]) : "r"(a));
}
__device__ __forceinline__ void ldsm2t(u32* f, u32 a) {
    asm volatile("ldmatrix.sync.aligned.m8n8.x2.trans.shared.b16 {%0,%1}, [%2];"
                 : "=r"(f[0]), "=r"(f[1]) : "r"(a));
}
__device__ __forceinline__ void mma_bf16(float* c, const u32* a, const u32* b) {
    asm volatile(
        "mma.sync.aligned.m16n8k16.row.col.f32.bf16.bf16.f32 "
        "{%0,%1,%2,%3}, {%4,%5,%6,%7}, {%8,%9}, {%0,%1,%2,%3};"
        : "+f"(c[0]), "+f"(c[1]), "+f"(c[2]), "+f"(c[3])
        : "r"(a[0]), "r"(a[1]), "r"(a[2]), "r"(a[3]), "r"(b[0]), "r"(b[1]));
}

// ---------------- smem layout (byte offsets, bf16 tiles) ----------------
// X/h1: [128 rows][stride 144B]  (72 bf16/row, 64 valid)
// W/h2: [64 or 128 rows][stride 144B]
// At:   [128 rows][stride 272B]  (136 bf16/row, 128 valid)
static constexpr u32 RS64  = 144;   // row stride for 64-wide tiles
static constexpr u32 RS128 = 272;   // row stride for 128-wide tiles

static constexpr u32 OFF_XHI  = 0;        // 18432  (also At-hi later, 34816)
static constexpr u32 OFF_XLO  = 18432;    // 18432
static constexpr u32 OFF_W1HI = 36864;    // 9216   (also h2hi later, 18432)
static constexpr u32 OFF_W1LO = 46080;    // 9216
static constexpr u32 OFF_W2HI = 55296;    // 9216   (also h2lo later, 18432)
static constexpr u32 OFF_W2LO = 64512;    // 9216
static constexpr u32 OFF_H2HI = 36864;
static constexpr u32 OFF_H2LO = 55296;
static constexpr u32 OFF_ATHI = 0;        // 34816
static constexpr u32 OFF_ATLO = 73728;    // 34816
static constexpr u32 OFF_B1   = 108544;   // 256
static constexpr u32 OFF_B2   = 108800;   // 256
static constexpr u32 SMEM_BYTES = 109056;

// =============== prep: A[b][k][j] -> At bf16 hi/lo images ===============
__global__ void prep_At(const float* __restrict__ A)
{
    __shared__ float tile[32][33];
    const int b = blockIdx.z, k0 = blockIdx.x * 32, j0 = blockIdx.y * 32;
    const int tx = threadIdx.x & 31, ty = threadIdx.x >> 5;   // ty: 0..7

    const float* Ab = A + ((size_t)b * NN + k0) * NN + j0;
    #pragma unroll
    for (int s = 0; s < 4; ++s)
        tile[ty + 8 * s][tx] = Ab[(ty + 8 * s) * NN + tx];
    __syncthreads();

    const int j = threadIdx.x >> 3;   // 0..31
    const int kq = threadIdx.x & 7;   // 4 k values each
    float v[4];
    #pragma unroll
    for (int s = 0; s < 4; ++s) v[s] = tile[kq * 4 + s][j];

    uint2 hi = make_uint2(pack_bf(v[0], v[1]), pack_bf(v[2], v[3]));
    uint2 lo = make_uint2(pack_bf(v[0] - bf_round(v[0]), v[1] - bf_round(v[1])),
                          pack_bf(v[2] - bf_round(v[2]), v[3] - bf_round(v[3])));
    size_t off = (size_t)(j0 + j) * RS128 + (size_t)(k0 + kq * 4) * 2;
    *reinterpret_cast<uint2*>(&g_Aimg[b][0][off]) = hi;
    *reinterpret_cast<uint2*>(&g_Aimg[b][1][off]) = lo;
}

// =============== warp GEMM: C[16 x 64] += A[16 x 16K] * B[16K x 64] ===============
// aHi/aLo: smem base (already offset to this warp's row0), row stride aRS.
// bHi/bLo: smem base of B [k][n] row-major, row stride bRS.
__device__ __forceinline__ void gemm_warp(u32 aHi, u32 aLo, u32 aRS,
                                          u32 bHi, u32 bLo, u32 bRS,
                                          int ksteps, int lane, float acc[8][4])
{
    const u32 aoff = (u32)(lane & 15) * aRS + (u32)(lane >> 4) * 16;
    const u32 boff = (u32)(lane & 15) * bRS;
    for (int ks = 0; ks < ksteps; ++ks) {
        u32 fah[4], fal[4];
        ldsm4(fah, aHi + aoff + (u32)ks * 32);
        ldsm4(fal, aLo + aoff + (u32)ks * 32);
        const u32 bb = (u32)ks * 16 * bRS + boff;
        #pragma unroll
        for (int n0 = 0; n0 < 8; ++n0) {
            u32 fbh[2], fbl[2];
            ldsm2t(fbh, bHi + bb + (u32)n0 * 16);
            ldsm2t(fbl, bLo + bb + (u32)n0 * 16);
            mma_bf16(acc[n0], fah, fbh);
            mma_bf16(acc[n0], fah, fbl);
            mma_bf16(acc[n0], fal, fbh);
        }
    }
}

__device__ __forceinline__ void zero_acc(float acc[8][4]) {
    #pragma unroll
    for (int n = 0; n < 8; ++n)
        #pragma unroll
        for (int q = 0; q < 4; ++q) acc[n][q] = 0.0f;
}

// bias + relu + bf16 hi/lo split, store into [row][RS64] smem tiles
__device__ __forceinline__ void store_relu_split(const float acc[8][4], u32 sb, u32 biasOff,
                                                 u32 dstHi, u32 dstLo, int lane, int row0)
{
    const int r  = row0 + (lane >> 2);
    const int cb = 2 * (lane & 3);
    #pragma unroll
    for (int n0 = 0; n0 < 8; ++n0) {
        const int col = n0 * 8 + cb;
        float bz0, bz1;
        lds64f(bz0, bz1, sb + biasOff + (u32)col * 4);
        float v0 = fmaxf(acc[n0][0] + bz0, 0.0f);
        float v1 = fmaxf(acc[n0][1] + bz1, 0.0f);
        float v2 = fmaxf(acc[n0][2] + bz0, 0.0f);
        float v3 = fmaxf(acc[n0][3] + bz1, 0.0f);
        const u32 a0 = sb + dstHi + (u32)r * RS64 + (u32)col * 2;
        const u32 a1 = a0 + 8u * RS64;
        const u32 dlo = dstLo - dstHi;
        sts32(a0, pack_bf(v0, v1));
        sts32(a1, pack_bf(v2, v3));
        sts32(a0 + dlo, pack_bf(v0 - bf_round(v0), v1 - bf_round(v1)));
        sts32(a1 + dlo, pack_bf(v2 - bf_round(v2), v3 - bf_round(v3)));
    }
}

// =============== main fused kernel ===============
__global__ __launch_bounds__(256, 2)
void crosssubg_mma_kernel(const float* __restrict__ X,
                          const float* __restrict__ W1,
                          const float* __restrict__ b1,
                          const float* __restrict__ W2,
                          const float* __restrict__ b2,
                          float* __restrict__ out)
{
    extern __shared__ __align__(1024) unsigned char smraw[];
    const u32 sb = smem_u32(smraw);

    const int i    = blockIdx.x;
    const int b    = blockIdx.y;
    const int tid  = (int)threadIdx.x;
    const int wid  = tid >> 5;
    const int lane = tid & 31;
    const int row0 = wid * 16;
    const size_t tile = (size_t)(b * NN + i);

    // ---- Phase 0: stage X (split bf16), W1/W2 (split), biases ----
    {
        const float4* gX4 = (const float4*)(X + tile * (NN * DD));   // 2048 float4
        #pragma unroll
        for (int it = 0; it < 8; ++it) {
            int t = tid + it * 256;
            float4 v = gX4[t];
            int k = t >> 4, d0 = (t & 15) * 4;
            u32 off = (u32)k * RS64 + (u32)d0 * 2;
            sts64(sb + OFF_XHI + off, pack_bf(v.x, v.y), pack_bf(v.z, v.w));
            sts64(sb + OFF_XLO + off,
                  pack_bf(v.x - bf_round(v.x), v.y - bf_round(v.y)),
                  pack_bf(v.z - bf_round(v.z), v.w - bf_round(v.w)));
        }
        #pragma unroll
        for (int it = 0; it < 32; ++it) {
            int t = tid + it * 256;                 // 0..8191
            int r = t & 4095;
            float v = (t < 4096) ? __ldg(&W1[r]) : __ldg(&W2[r]);
            int d = r >> 6, e = r & 63;
            u32 offH = ((t < 4096) ? OFF_W1HI : OFF_W2HI) + (u32)d * RS64 + (u32)e * 2;
            float h = bf_round(v);
            sts16(sb + offH, bf16bits(h));
            sts16(sb + offH + 9216, bf16bits(v - h));
        }
        if (tid < 64)       sts32(sb + OFF_B1 + (u32)tid * 4, __float_as_uint(__ldg(&b1[tid])));
        else if (tid < 128) sts32(sb + OFF_B2 + (u32)(tid - 64) * 4, __float_as_uint(__ldg(&b2[tid - 64])));
    }
    __syncthreads();

    float acc[8][4];

    // ---- GEMM1: h1[k][e] = relu(X W1 + b1), M=128 N=64 K=64 ----
    zero_acc(acc);
    gemm_warp(sb + OFF_XHI + (u32)row0 * RS64, sb + OFF_XLO + (u32)row0 * RS64, RS64,
              sb + OFF_W1HI, sb + OFF_W1LO, RS64, 4, lane, acc);
    __syncthreads();                       // all G1 reads of X done
    store_relu_split(acc, sb, OFF_B1, OFF_XHI, OFF_XLO, lane, row0);   // h1 over X
    __syncthreads();

    // ---- GEMM2: h2[k][d] = relu(h1 W2 + b2) ----
    zero_acc(acc);
    gemm_warp(sb + OFF_XHI + (u32)row0 * RS64, sb + OFF_XLO + (u32)row0 * RS64, RS64,
              sb + OFF_W2HI, sb + OFF_W2LO, RS64, 4, lane, acc);
    __syncthreads();                       // all G2 reads of h1/W2 done
    store_relu_split(acc, sb, OFF_B2, OFF_H2HI, OFF_H2LO, lane, row0); // h2 over W
    // stage At (hi over h1 region, lo fresh) — h1 dead after the sync above
    {
        const uint4* gH = (const uint4*)&g_Aimg[b][0][0];   // 2176 uint4
        const uint4* gL = (const uint4*)&g_Aimg[b][1][0];
        #pragma unroll
        for (int it = 0; it < 9; ++it) {
            int t = tid + it * 256;
            if (t < 2176) {
                uint4 v = gH[t];
                sts128(sb + OFF_ATHI + (u32)t * 16, v.x, v.y, v.z, v.w);
                uint4 w = gL[t];
                sts128(sb + OFF_ATLO + (u32)t * 16, w.x, w.y, w.z, w.w);
            }
        }
    }
    __syncthreads();

    // ---- GEMM3: out[j][d] = sum_k At[j][k] h2[k][d], M=128 N=64 K=128 ----
    zero_acc(acc);
    gemm_warp(sb + OFF_ATHI + (u32)row0 * RS128, sb + OFF_ATLO + (u32)row0 * RS128, RS128,
              sb + OFF_H2HI, sb + OFF_H2LO, RS64, 8, lane, acc);

    // ---- store to global ----
    {
        float* gO = out + tile * (NN * DD);
        const int j  = row0 + (lane >> 2);
        const int cb = 2 * (lane & 3);
        #pragma unroll
        for (int n0 = 0; n0 < 8; ++n0) {
            const int col = n0 * 8 + cb;
            *(float2*)(gO + (size_t)j * DD + col)       = make_float2(acc[n0][0], acc[n0][1]);
            *(float2*)(gO + (size_t)(j + 8) * DD + col) = make_float2(acc[n0][2], acc[n0][3]);
        }
    }
}

extern "C" void kernel_launch(void* const* d_in, const int* in_sizes, int n_in,
                              void* d_out, int out_size)
{
    const float *X = nullptr, *A = nullptr, *W1 = nullptr, *b1 = nullptr,
                *W2 = nullptr, *b2 = nullptr;
    for (int idx = 0; idx < n_in; ++idx) {
        const float* p = (const float*)d_in[idx];
        int s = in_sizes[idx];
        if      (s == NB * NN * NN * DD) X = p;
        else if (s == NB * NN * NN)      A = p;
        else if (s == DD * DD)           { if (!W1) W1 = p; else W2 = p; }
        else if (s == DD)                { if (!b1) b1 = p; else b2 = p; }
    }

    prep_At<<<dim3(4, 4, 32), 256>>>(A);

    cudaFuncSetAttribute(crosssubg_mma_kernel,
                         cudaFuncAttributeMaxDynamicSharedMemorySize, SMEM_BYTES);
    dim3 grid(NN, NB);
    crosssubg_mma_kernel<<<grid, 256, SMEM_BYTES>>>(X, W1, b1, W2, b2, (float*)d_out);
}

// round 4
// speedup vs baseline: 4.4501x; 1.4395x over previous
#include <cuda_runtime.h>
#include <cuda_bf16.h>
#include <cuda_fp16.h>
#include <cstdint>

typedef uint32_t u32;
typedef uint64_t u64;

static constexpr int NB = 32, NN = 128, DD = 64;

// Precomputed A-transpose fp16 image: At[j][k] = A[b][k][j],
// 128 rows, row stride 136 fp16 (272B), 128 valid k + pad.
__device__ __align__(16) unsigned char g_Ah[32][34816];

// ---------------- helpers ----------------
__device__ __forceinline__ u32 smem_u32(const void* p) {
    u32 a;
    asm("{ .reg .u64 t; cvta.to.shared.u64 t, %1; cvt.u32.u64 %0, t; }" : "=r"(a) : "l"(p));
    return a;
}
__device__ __forceinline__ u32 pack_bf(float lo, float hi) {
    u32 r;  // r = {hi16=cvt(hi), lo16=cvt(lo)}
    asm("cvt.rn.bf16x2.f32 %0, %1, %2;" : "=r"(r) : "f"(hi), "f"(lo));
    return r;
}
__device__ __forceinline__ u32 pack_h16(float lo, float hi) {
    u32 r;
    asm("cvt.rn.f16x2.f32 %0, %1, %2;" : "=r"(r) : "f"(hi), "f"(lo));
    return r;
}
__device__ __forceinline__ float bf_round(float v) {
    __nv_bfloat16 h = __float2bfloat16(v);
    return __bfloat162float(h);
}
__device__ __forceinline__ void sts32(u32 a, u32 v) {
    asm volatile("st.shared.b32 [%0], %1;" :: "r"(a), "r"(v) : "memory");
}
__device__ __forceinline__ void sts64(u32 a, u32 x, u32 y) {
    asm volatile("st.shared.v2.b32 [%0], {%1,%2};" :: "r"(a), "r"(x), "r"(y) : "memory");
}
__device__ __forceinline__ void sts128(u32 a, u32 x, u32 y, u32 z, u32 w) {
    asm volatile("st.shared.v4.b32 [%0], {%1,%2,%3,%4};" :: "r"(a), "r"(x), "r"(y), "r"(z), "r"(w) : "memory");
}
__device__ __forceinline__ void lds64f(float& x, float& y, u32 a) {
    asm volatile("ld.shared.v2.f32 {%0,%1}, [%2];" : "=f"(x), "=f"(y) : "r"(a));
}
__device__ __forceinline__ void ldsm4(u32* f, u32 a) {
    asm volatile("ldmatrix.sync.aligned.m8n8.x4.shared.b16 {%0,%1,%2,%3}, [%4];"
                 : "=r"(f[0]), "=r"(f[1]), "=r"(f[2]), "=r"(f[3]) : "r"(a));
}
__device__ __forceinline__ void ldsm4t(u32* f, u32 a) {
    asm volatile("ldmatrix.sync.aligned.m8n8.x4.trans.shared.b16 {%0,%1,%2,%3}, [%4];"
                 : "=r"(f[0]), "=r"(f[1]), "=r"(f[2]), "=r"(f[3]) : "r"(a));
}
__device__ __forceinline__ void mma_bf16(float* c, const u32* a, const u32* b) {
    asm volatile(
        "mma.sync.aligned.m16n8k16.row.col.f32.bf16.bf16.f32 "
        "{%0,%1,%2,%3}, {%4,%5,%6,%7}, {%8,%9}, {%0,%1,%2,%3};"
        : "+f"(c[0]), "+f"(c[1]), "+f"(c[2]), "+f"(c[3])
        : "r"(a[0]), "r"(a[1]), "r"(a[2]), "r"(a[3]), "r"(b[0]), "r"(b[1]));
}
__device__ __forceinline__ void mma_f16(float* c, const u32* a, const u32* b) {
    asm volatile(
        "mma.sync.aligned.m16n8k16.row.col.f32.f16.f16.f32 "
        "{%0,%1,%2,%3}, {%4,%5,%6,%7}, {%8,%9}, {%0,%1,%2,%3};"
        : "+f"(c[0]), "+f"(c[1]), "+f"(c[2]), "+f"(c[3])
        : "r"(a[0]), "r"(a[1]), "r"(a[2]), "r"(a[3]), "r"(b[0]), "r"(b[1]));
}

// ---------------- smem layout ----------------
static constexpr u32 RS64  = 144;   // 64-wide bf16/fp16 tile row stride (bytes)
static constexpr u32 RS128 = 272;   // 128-wide tile row stride

static constexpr u32 OFF_XHI  = 0;        // 18432  (X hi / h1 hi / At fp16 later)
static constexpr u32 OFF_XLO  = 18432;    // 18432  (X lo / h1 lo)
static constexpr u32 OFF_W1HI = 36864;    // 9216   (later h2 fp16, 18432)
static constexpr u32 OFF_W1LO = 46080;    // 9216
static constexpr u32 OFF_W2HI = 55296;    // 9216
static constexpr u32 OFF_W2LO = 64512;    // 9216
static constexpr u32 OFF_H2   = 36864;    // h2 fp16 single image (18432)
static constexpr u32 OFF_AT   = 0;        // At fp16 (34816, over X region)
static constexpr u32 OFF_B1   = 73728;
static constexpr u32 OFF_B2   = 73984;
static constexpr u32 SMEM_BYTES = 74240;

// =============== prep: A[b][k][j] -> At fp16 image ===============
__global__ void prep_At(const float* __restrict__ A)
{
    __shared__ float tile[32][33];
    const int b = blockIdx.z, k0 = blockIdx.x * 32, j0 = blockIdx.y * 32;
    const int tx = threadIdx.x & 31, ty = threadIdx.x >> 5;   // ty: 0..7

    const float* Ab = A + ((size_t)b * NN + k0) * NN + j0;
    #pragma unroll
    for (int s = 0; s < 4; ++s)
        tile[ty + 8 * s][tx] = Ab[(ty + 8 * s) * NN + tx];
    __syncthreads();

    const int j  = threadIdx.x >> 3;   // 0..31
    const int kq = threadIdx.x & 7;    // 4 k values each
    float v[4];
    #pragma unroll
    for (int s = 0; s < 4; ++s) v[s] = tile[kq * 4 + s][j];

    uint2 h = make_uint2(pack_h16(v[0], v[1]), pack_h16(v[2], v[3]));
    size_t off = (size_t)(j0 + j) * RS128 + (size_t)(k0 + kq * 4) * 2;
    *reinterpret_cast<uint2*>(&g_Ah[b][off]) = h;
}

// =============== 3-term split bf16 warp GEMM (x4 B loads) ===============
__device__ __forceinline__ void gemm_warp3(u32 aHi, u32 aLo, u32 aRS,
                                           u32 bHi, u32 bLo, u32 bRS,
                                           int ksteps, int lane, float acc[8][4])
{
    const u32 aoff = (u32)(lane & 15) * aRS + (u32)(lane >> 4) * 16;
    const u32 boff = (u32)(lane & 15) * bRS + (u32)(lane >> 4) * 16;
    for (int ks = 0; ks < ksteps; ++ks) {
        u32 fah[4], fal[4];
        ldsm4(fah, aHi + aoff + (u32)ks * 32);
        ldsm4(fal, aLo + aoff + (u32)ks * 32);
        const u32 bb = (u32)ks * 16 * bRS + boff;
        #pragma unroll
        for (int np = 0; np < 4; ++np) {
            u32 fbh[4], fbl[4];
            ldsm4t(fbh, bHi + bb + (u32)np * 32);
            ldsm4t(fbl, bLo + bb + (u32)np * 32);
            mma_bf16(acc[2 * np],     fah, fbh);
            mma_bf16(acc[2 * np],     fah, fbl);
            mma_bf16(acc[2 * np],     fal, fbh);
            mma_bf16(acc[2 * np + 1], fah, fbh + 2);
            mma_bf16(acc[2 * np + 1], fah, fbl + 2);
            mma_bf16(acc[2 * np + 1], fal, fbh + 2);
        }
    }
}

// =============== single-term fp16 warp GEMM (GEMM3) ===============
__device__ __forceinline__ void gemm_warp_h16(u32 aBase, u32 aRS,
                                              u32 bBase, u32 bRS,
                                              int ksteps, int lane, float acc[8][4])
{
    const u32 aoff = (u32)(lane & 15) * aRS + (u32)(lane >> 4) * 16;
    const u32 boff = (u32)(lane & 15) * bRS + (u32)(lane >> 4) * 16;
    for (int ks = 0; ks < ksteps; ++ks) {
        u32 fa[4];
        ldsm4(fa, aBase + aoff + (u32)ks * 32);
        const u32 bb = (u32)ks * 16 * bRS + boff;
        #pragma unroll
        for (int np = 0; np < 4; ++np) {
            u32 fb[4];
            ldsm4t(fb, bBase + bb + (u32)np * 32);
            mma_f16(acc[2 * np],     fa, fb);
            mma_f16(acc[2 * np + 1], fa, fb + 2);
        }
    }
}

__device__ __forceinline__ void zero_acc(float acc[8][4]) {
    #pragma unroll
    for (int n = 0; n < 8; ++n)
        #pragma unroll
        for (int q = 0; q < 4; ++q) acc[n][q] = 0.0f;
}

// bias + relu + bf16 hi/lo split store (h1)
__device__ __forceinline__ void store_relu_split(const float acc[8][4], u32 sb, u32 biasOff,
                                                 u32 dstHi, u32 dstLo, int lane, int row0)
{
    const int r  = row0 + (lane >> 2);
    const int cb = 2 * (lane & 3);
    #pragma unroll
    for (int n0 = 0; n0 < 8; ++n0) {
        const int col = n0 * 8 + cb;
        float bz0, bz1;
        lds64f(bz0, bz1, sb + biasOff + (u32)col * 4);
        float v0 = fmaxf(acc[n0][0] + bz0, 0.0f);
        float v1 = fmaxf(acc[n0][1] + bz1, 0.0f);
        float v2 = fmaxf(acc[n0][2] + bz0, 0.0f);
        float v3 = fmaxf(acc[n0][3] + bz1, 0.0f);
        const u32 a0 = sb + dstHi + (u32)r * RS64 + (u32)col * 2;
        const u32 a1 = a0 + 8u * RS64;
        const u32 dlo = dstLo - dstHi;
        sts32(a0, pack_bf(v0, v1));
        sts32(a1, pack_bf(v2, v3));
        sts32(a0 + dlo, pack_bf(v0 - bf_round(v0), v1 - bf_round(v1)));
        sts32(a1 + dlo, pack_bf(v2 - bf_round(v2), v3 - bf_round(v3)));
    }
}

// bias + relu + fp16 single store (h2)
__device__ __forceinline__ void store_relu_h16(const float acc[8][4], u32 sb, u32 biasOff,
                                               u32 dst, int lane, int row0)
{
    const int r  = row0 + (lane >> 2);
    const int cb = 2 * (lane & 3);
    #pragma unroll
    for (int n0 = 0; n0 < 8; ++n0) {
        const int col = n0 * 8 + cb;
        float bz0, bz1;
        lds64f(bz0, bz1, sb + biasOff + (u32)col * 4);
        float v0 = fmaxf(acc[n0][0] + bz0, 0.0f);
        float v1 = fmaxf(acc[n0][1] + bz1, 0.0f);
        float v2 = fmaxf(acc[n0][2] + bz0, 0.0f);
        float v3 = fmaxf(acc[n0][3] + bz1, 0.0f);
        const u32 a0 = sb + dst + (u32)r * RS64 + (u32)col * 2;
        sts32(a0,             pack_h16(v0, v1));
        sts32(a0 + 8u * RS64, pack_h16(v2, v3));
    }
}

// =============== main fused kernel ===============
__global__ __launch_bounds__(256, 3)
void crosssubg_mma_kernel(const float* __restrict__ X,
                          const float* __restrict__ W1,
                          const float* __restrict__ b1,
                          const float* __restrict__ W2,
                          const float* __restrict__ b2,
                          float* __restrict__ out)
{
    extern __shared__ __align__(1024) unsigned char smraw[];
    const u32 sb = smem_u32(smraw);

    const int i    = blockIdx.x;
    const int b    = blockIdx.y;
    const int tid  = (int)threadIdx.x;
    const int wid  = tid >> 5;
    const int lane = tid & 31;
    const int row0 = wid * 16;
    const size_t tile = (size_t)(b * NN + i);

    // ---- Phase 0: stage X (bf16 split), W1/W2 (bf16 split), biases ----
    {
        const float4* gX4 = (const float4*)(X + tile * (NN * DD));   // 2048 float4
        #pragma unroll
        for (int it = 0; it < 8; ++it) {
            int t = tid + it * 256;
            float4 v = gX4[t];
            int k = t >> 4, d0 = (t & 15) * 4;
            u32 off = (u32)k * RS64 + (u32)d0 * 2;
            sts64(sb + OFF_XHI + off, pack_bf(v.x, v.y), pack_bf(v.z, v.w));
            sts64(sb + OFF_XLO + off,
                  pack_bf(v.x - bf_round(v.x), v.y - bf_round(v.y)),
                  pack_bf(v.z - bf_round(v.z), v.w - bf_round(v.w)));
        }
        const float4* gW1 = (const float4*)W1;   // 1024 each
        const float4* gW2 = (const float4*)W2;
        #pragma unroll
        for (int it = 0; it < 8; ++it) {
            int t = tid + it * 256;              // 0..2047
            int sel = t >> 10;
            int r = t & 1023;
            float4 v = sel ? gW2[r] : gW1[r];
            int d = r >> 4, e0 = (r & 15) * 4;
            u32 offH = (sel ? OFF_W2HI : OFF_W1HI) + (u32)d * RS64 + (u32)e0 * 2;
            sts64(sb + offH, pack_bf(v.x, v.y), pack_bf(v.z, v.w));
            sts64(sb + offH + 9216,
                  pack_bf(v.x - bf_round(v.x), v.y - bf_round(v.y)),
                  pack_bf(v.z - bf_round(v.z), v.w - bf_round(v.w)));
        }
        if (tid < 64)       sts32(sb + OFF_B1 + (u32)tid * 4, __float_as_uint(__ldg(&b1[tid])));
        else if (tid < 128) sts32(sb + OFF_B2 + (u32)(tid - 64) * 4, __float_as_uint(__ldg(&b2[tid - 64])));
    }
    __syncthreads();

    float acc[8][4];

    // ---- GEMM1: h1 = relu(X W1 + b1)  (M=128 N=64 K=64, 3-term bf16) ----
    zero_acc(acc);
    gemm_warp3(sb + OFF_XHI + (u32)row0 * RS64, sb + OFF_XLO + (u32)row0 * RS64, RS64,
               sb + OFF_W1HI, sb + OFF_W1LO, RS64, 4, lane, acc);
    __syncthreads();
    store_relu_split(acc, sb, OFF_B1, OFF_XHI, OFF_XLO, lane, row0);   // h1 over X
    __syncthreads();

    // ---- GEMM2: h2 = relu(h1 W2 + b2)  (3-term bf16) ----
    zero_acc(acc);
    gemm_warp3(sb + OFF_XHI + (u32)row0 * RS64, sb + OFF_XLO + (u32)row0 * RS64, RS64,
               sb + OFF_W2HI, sb + OFF_W2LO, RS64, 4, lane, acc);
    __syncthreads();
    store_relu_h16(acc, sb, OFF_B2, OFF_H2, lane, row0);               // h2 fp16 over W1
    // stage At fp16 over X/h1 region (h1 dead after the sync above)
    {
        const uint4* gA = (const uint4*)&g_Ah[b][0];   // 2176 uint4
        #pragma unroll
        for (int it = 0; it < 9; ++it) {
            int t = tid + it * 256;
            if (t < 2176) {
                uint4 v = gA[t];
                sts128(sb + OFF_AT + (u32)t * 16, v.x, v.y, v.z, v.w);
            }
        }
    }
    __syncthreads();

    // ---- GEMM3: out[j][d] = sum_k At[j][k] h2[k][d]  (M=128 N=64 K=128, fp16) ----
    zero_acc(acc);
    gemm_warp_h16(sb + OFF_AT + (u32)row0 * RS128, RS128,
                  sb + OFF_H2, RS64, 8, lane, acc);

    // ---- store to global ----
    {
        float* gO = out + tile * (NN * DD);
        const int j  = row0 + (lane >> 2);
        const int cb = 2 * (lane & 3);
        #pragma unroll
        for (int n0 = 0; n0 < 8; ++n0) {
            const int col = n0 * 8 + cb;
            *(float2*)(gO + (size_t)j * DD + col)       = make_float2(acc[n0][0], acc[n0][1]);
            *(float2*)(gO + (size_t)(j + 8) * DD + col) = make_float2(acc[n0][2], acc[n0][3]);
        }
    }
}

extern "C" void kernel_launch(void* const* d_in, const int* in_sizes, int n_in,
                              void* d_out, int out_size)
{
    const float *X = nullptr, *A = nullptr, *W1 = nullptr, *b1 = nullptr,
                *W2 = nullptr, *b2 = nullptr;
    for (int idx = 0; idx < n_in; ++idx) {
        const float* p = (const float*)d_in[idx];
        int s = in_sizes[idx];
        if      (s == NB * NN * NN * DD) X = p;
        else if (s == NB * NN * NN)      A = p;
        else if (s == DD * DD)           { if (!W1) W1 = p; else W2 = p; }
        else if (s == DD)                { if (!b1) b1 = p; else b2 = p; }
    }

    prep_At<<<dim3(4, 4, 32), 256>>>(A);

    cudaFuncSetAttribute(crosssubg_mma_kernel,
                         cudaFuncAttributeMaxDynamicSharedMemorySize, SMEM_BYTES);
    dim3 grid(NN, NB);
    crosssubg_mma_kernel<<<grid, 256, SMEM_BYTES>>>(X, W1, b1, W2, b2, (float*)d_out);
}

// round 5
// speedup vs baseline: 5.7522x; 1.2926x over previous
#include <cuda_runtime.h>
#include <cuda_fp16.h>
#include <cstdint>

typedef uint32_t u32;

static constexpr int NB = 32, NN = 128, DD = 64;

// Precomputed A-transpose fp16 image: At[j][k] = A[b][k][j],
// 128 rows, row stride 136 fp16 (272B), 128 valid k + pad.
__device__ __align__(16) unsigned char g_Ah[32][34816];

// ---------------- helpers ----------------
__device__ __forceinline__ u32 smem_u32(const void* p) {
    u32 a;
    asm("{ .reg .u64 t; cvta.to.shared.u64 t, %1; cvt.u32.u64 %0, t; }" : "=r"(a) : "l"(p));
    return a;
}
__device__ __forceinline__ u32 pack_h16(float lo, float hi) {
    u32 r;
    asm("cvt.rn.f16x2.f32 %0, %1, %2;" : "=r"(r) : "f"(hi), "f"(lo));
    return r;
}
__device__ __forceinline__ void sts32(u32 a, u32 v) {
    asm volatile("st.shared.b32 [%0], %1;" :: "r"(a), "r"(v) : "memory");
}
__device__ __forceinline__ void sts64(u32 a, u32 x, u32 y) {
    asm volatile("st.shared.v2.b32 [%0], {%1,%2};" :: "r"(a), "r"(x), "r"(y) : "memory");
}
__device__ __forceinline__ void sts128(u32 a, u32 x, u32 y, u32 z, u32 w) {
    asm volatile("st.shared.v4.b32 [%0], {%1,%2,%3,%4};" :: "r"(a), "r"(x), "r"(y), "r"(z), "r"(w) : "memory");
}
__device__ __forceinline__ void lds64f(float& x, float& y, u32 a) {
    asm volatile("ld.shared.v2.f32 {%0,%1}, [%2];" : "=f"(x), "=f"(y) : "r"(a));
}
__device__ __forceinline__ void ldsm4(u32* f, u32 a) {
    asm volatile("ldmatrix.sync.aligned.m8n8.x4.shared.b16 {%0,%1,%2,%3}, [%4];"
                 : "=r"(f[0]), "=r"(f[1]), "=r"(f[2]), "=r"(f[3]) : "r"(a));
}
__device__ __forceinline__ void ldsm4t(u32* f, u32 a) {
    asm volatile("ldmatrix.sync.aligned.m8n8.x4.trans.shared.b16 {%0,%1,%2,%3}, [%4];"
                 : "=r"(f[0]), "=r"(f[1]), "=r"(f[2]), "=r"(f[3]) : "r"(a));
}
__device__ __forceinline__ void mma_f16(float* c, const u32* a, const u32* b) {
    asm volatile(
        "mma.sync.aligned.m16n8k16.row.col.f32.f16.f16.f32 "
        "{%0,%1,%2,%3}, {%4,%5,%6,%7}, {%8,%9}, {%0,%1,%2,%3};"
        : "+f"(c[0]), "+f"(c[1]), "+f"(c[2]), "+f"(c[3])
        : "r"(a[0]), "r"(a[1]), "r"(a[2]), "r"(a[3]), "r"(b[0]), "r"(b[1]));
}

// ---------------- smem layout ----------------
static constexpr u32 RS64  = 144;   // 64-wide fp16 tile row stride (bytes)
static constexpr u32 RS128 = 272;   // 128-wide tile row stride

static constexpr u32 OFF_X  = 0;        // 18432 (X / h1; At spans 0..34816 later)
static constexpr u32 OFF_W1 = 18432;    // 9216
static constexpr u32 OFF_W2 = 27648;    // 9216
static constexpr u32 OFF_AT = 0;        // 34816 (over X + W1 + 7KB of W2, all dead)
static constexpr u32 OFF_H2 = 36864;    // 18432
static constexpr u32 OFF_B1 = 55296;    // 256
static constexpr u32 OFF_B2 = 55552;    // 256
static constexpr u32 SMEM_BYTES = 55808;

// =============== prep: A[b][k][j] -> At fp16 image ===============
__global__ void prep_At(const float* __restrict__ A)
{
    __shared__ float tile[32][33];
    const int b = blockIdx.z, k0 = blockIdx.x * 32, j0 = blockIdx.y * 32;
    const int tx = threadIdx.x & 31, ty = threadIdx.x >> 5;   // ty: 0..7

    const float* Ab = A + ((size_t)b * NN + k0) * NN + j0;
    #pragma unroll
    for (int s = 0; s < 4; ++s)
        tile[ty + 8 * s][tx] = Ab[(ty + 8 * s) * NN + tx];
    __syncthreads();

    const int j  = threadIdx.x >> 3;   // 0..31
    const int kq = threadIdx.x & 7;    // 4 k values each
    float v[4];
    #pragma unroll
    for (int s = 0; s < 4; ++s) v[s] = tile[kq * 4 + s][j];

    uint2 h = make_uint2(pack_h16(v[0], v[1]), pack_h16(v[2], v[3]));
    size_t off = (size_t)(j0 + j) * RS128 + (size_t)(k0 + kq * 4) * 2;
    *reinterpret_cast<uint2*>(&g_Ah[b][off]) = h;
}

// =============== single-term fp16 warp GEMM ===============
// C[16 x 64] += A[16 x 16K] * B[16K x 64]
__device__ __forceinline__ void gemm_warp_h16(u32 aBase, u32 aRS,
                                              u32 bBase, u32 bRS,
                                              int ksteps, int lane, float acc[8][4])
{
    const u32 aoff = (u32)(lane & 15) * aRS + (u32)(lane >> 4) * 16;
    const u32 boff = (u32)(lane & 15) * bRS + (u32)(lane >> 4) * 16;
    for (int ks = 0; ks < ksteps; ++ks) {
        u32 fa[4];
        ldsm4(fa, aBase + aoff + (u32)ks * 32);
        const u32 bb = (u32)ks * 16 * bRS + boff;
        #pragma unroll
        for (int np = 0; np < 4; ++np) {
            u32 fb[4];
            ldsm4t(fb, bBase + bb + (u32)np * 32);
            mma_f16(acc[2 * np],     fa, fb);
            mma_f16(acc[2 * np + 1], fa, fb + 2);
        }
    }
}

__device__ __forceinline__ void zero_acc(float acc[8][4]) {
    #pragma unroll
    for (int n = 0; n < 8; ++n)
        #pragma unroll
        for (int q = 0; q < 4; ++q) acc[n][q] = 0.0f;
}

// bias + relu + fp16 store into [row][RS64] smem tile
__device__ __forceinline__ void store_relu_h16(const float acc[8][4], u32 sb, u32 biasOff,
                                               u32 dst, int lane, int row0)
{
    const int r  = row0 + (lane >> 2);
    const int cb = 2 * (lane & 3);
    #pragma unroll
    for (int n0 = 0; n0 < 8; ++n0) {
        const int col = n0 * 8 + cb;
        float bz0, bz1;
        lds64f(bz0, bz1, sb + biasOff + (u32)col * 4);
        float v0 = fmaxf(acc[n0][0] + bz0, 0.0f);
        float v1 = fmaxf(acc[n0][1] + bz1, 0.0f);
        float v2 = fmaxf(acc[n0][2] + bz0, 0.0f);
        float v3 = fmaxf(acc[n0][3] + bz1, 0.0f);
        const u32 a0 = sb + dst + (u32)r * RS64 + (u32)col * 2;
        sts32(a0,             pack_h16(v0, v1));
        sts32(a0 + 8u * RS64, pack_h16(v2, v3));
    }
}

// =============== main fused kernel ===============
__global__ __launch_bounds__(256, 4)
void crosssubg_mma_kernel(const float* __restrict__ X,
                          const float* __restrict__ W1,
                          const float* __restrict__ b1,
                          const float* __restrict__ W2,
                          const float* __restrict__ b2,
                          float* __restrict__ out)
{
    extern __shared__ __align__(1024) unsigned char smraw[];
    const u32 sb = smem_u32(smraw);

    const int i    = blockIdx.x;
    const int b    = blockIdx.y;
    const int tid  = (int)threadIdx.x;
    const int wid  = tid >> 5;
    const int lane = tid & 31;
    const int row0 = wid * 16;
    const size_t tile = (size_t)(b * NN + i);

    // ---- Phase 0: stage X (fp16), W1/W2 (fp16), biases ----
    {
        const float4* gX4 = (const float4*)(X + tile * (NN * DD));   // 2048 float4
        #pragma unroll
        for (int it = 0; it < 8; ++it) {
            int t = tid + it * 256;
            float4 v = gX4[t];
            int k = t >> 4, d0 = (t & 15) * 4;
            sts64(sb + OFF_X + (u32)k * RS64 + (u32)d0 * 2,
                  pack_h16(v.x, v.y), pack_h16(v.z, v.w));
        }
        const float4* gW1 = (const float4*)W1;   // 1024 each
        const float4* gW2 = (const float4*)W2;
        #pragma unroll
        for (int it = 0; it < 8; ++it) {
            int t = tid + it * 256;              // 0..2047
            int sel = t >> 10;
            int r = t & 1023;
            float4 v = sel ? gW2[r] : gW1[r];
            int d = r >> 4, e0 = (r & 15) * 4;
            sts64(sb + (sel ? OFF_W2 : OFF_W1) + (u32)d * RS64 + (u32)e0 * 2,
                  pack_h16(v.x, v.y), pack_h16(v.z, v.w));
        }
        if (tid < 64)       sts32(sb + OFF_B1 + (u32)tid * 4, __float_as_uint(__ldg(&b1[tid])));
        else if (tid < 128) sts32(sb + OFF_B2 + (u32)(tid - 64) * 4, __float_as_uint(__ldg(&b2[tid - 64])));
    }
    __syncthreads();

    float acc[8][4];

    // ---- GEMM1: h1 = relu(X W1 + b1)  (M=128 N=64 K=64) ----
    zero_acc(acc);
    gemm_warp_h16(sb + OFF_X + (u32)row0 * RS64, RS64, sb + OFF_W1, RS64, 4, lane, acc);
    __syncthreads();                                   // all G1 reads of X done
    store_relu_h16(acc, sb, OFF_B1, OFF_X, lane, row0);   // h1 over X
    __syncthreads();

    // ---- GEMM2: h2 = relu(h1 W2 + b2) ----
    zero_acc(acc);
    gemm_warp_h16(sb + OFF_X + (u32)row0 * RS64, RS64, sb + OFF_W2, RS64, 4, lane, acc);
    __syncthreads();                                   // all G2 reads of h1/W2 done
    store_relu_h16(acc, sb, OFF_B2, OFF_H2, lane, row0);  // h2 into fresh region
    // stage At fp16 over X/h1 + W regions (all dead after the sync above)
    {
        const uint4* gA = (const uint4*)&g_Ah[b][0];   // 2176 uint4
        #pragma unroll
        for (int it = 0; it < 9; ++it) {
            int t = tid + it * 256;
            if (t < 2176) {
                uint4 v = gA[t];
                sts128(sb + OFF_AT + (u32)t * 16, v.x, v.y, v.z, v.w);
            }
        }
    }
    __syncthreads();

    // ---- GEMM3: out[j][d] = sum_k At[j][k] h2[k][d]  (M=128 N=64 K=128) ----
    zero_acc(acc);
    gemm_warp_h16(sb + OFF_AT + (u32)row0 * RS128, RS128, sb + OFF_H2, RS64, 8, lane, acc);

    // ---- store to global ----
    {
        float* gO = out + tile * (NN * DD);
        const int j  = row0 + (lane >> 2);
        const int cb = 2 * (lane & 3);
        #pragma unroll
        for (int n0 = 0; n0 < 8; ++n0) {
            const int col = n0 * 8 + cb;
            *(float2*)(gO + (size_t)j * DD + col)       = make_float2(acc[n0][0], acc[n0][1]);
            *(float2*)(gO + (size_t)(j + 8) * DD + col) = make_float2(acc[n0][2], acc[n0][3]);
        }
    }
}

extern "C" void kernel_launch(void* const* d_in, const int* in_sizes, int n_in,
                              void* d_out, int out_size)
{
    const float *X = nullptr, *A = nullptr, *W1 = nullptr, *b1 = nullptr,
                *W2 = nullptr, *b2 = nullptr;
    for (int idx = 0; idx < n_in; ++idx) {
        const float* p = (const float*)d_in[idx];
        int s = in_sizes[idx];
        if      (s == NB * NN * NN * DD) X = p;
        else if (s == NB * NN * NN)      A = p;
        else if (s == DD * DD)           { if (!W1) W1 = p; else W2 = p; }
        else if (s == DD)                { if (!b1) b1 = p; else b2 = p; }
    }

    prep_At<<<dim3(4, 4, 32), 256>>>(A);

    cudaFuncSetAttribute(crosssubg_mma_kernel,
                         cudaFuncAttributeMaxDynamicSharedMemorySize, SMEM_BYTES);
    dim3 grid(NN, NB);
    crosssubg_mma_kernel<<<grid, 256, SMEM_BYTES>>>(X, W1, b1, W2, b2, (float*)d_out);
}

// round 6
// speedup vs baseline: 7.0604x; 1.2274x over previous
#include <cuda_runtime.h>
#include <cuda_fp16.h>
#include <cstdint>

typedef uint32_t u32;

static constexpr int NB = 32, NN = 128, DD = 64;

// Precomputed A-transpose fp16 image: At[j][k] = A[b][k][j],
// 128 rows, row stride 136 fp16 (272B), 128 valid k + pad.
__device__ __align__(16) unsigned char g_Ah[32][34816];

// ---------------- helpers ----------------
__device__ __forceinline__ u32 smem_u32(const void* p) {
    u32 a;
    asm("{ .reg .u64 t; cvta.to.shared.u64 t, %1; cvt.u32.u64 %0, t; }" : "=r"(a) : "l"(p));
    return a;
}
__device__ __forceinline__ u32 pack_h16(float lo, float hi) {
    u32 r;
    asm("cvt.rn.f16x2.f32 %0, %1, %2;" : "=r"(r) : "f"(hi), "f"(lo));
    return r;
}
__device__ __forceinline__ void sts32(u32 a, u32 v) {
    asm volatile("st.shared.b32 [%0], %1;" :: "r"(a), "r"(v) : "memory");
}
__device__ __forceinline__ void sts64(u32 a, u32 x, u32 y) {
    asm volatile("st.shared.v2.b32 [%0], {%1,%2};" :: "r"(a), "r"(x), "r"(y) : "memory");
}
__device__ __forceinline__ void sts128(u32 a, u32 x, u32 y, u32 z, u32 w) {
    asm volatile("st.shared.v4.b32 [%0], {%1,%2,%3,%4};" :: "r"(a), "r"(x), "r"(y), "r"(z), "r"(w) : "memory");
}
__device__ __forceinline__ void lds64f(float& x, float& y, u32 a) {
    asm volatile("ld.shared.v2.f32 {%0,%1}, [%2];" : "=f"(x), "=f"(y) : "r"(a));
}
__device__ __forceinline__ void ldsm4(u32* f, u32 a) {
    asm volatile("ldmatrix.sync.aligned.m8n8.x4.shared.b16 {%0,%1,%2,%3}, [%4];"
                 : "=r"(f[0]), "=r"(f[1]), "=r"(f[2]), "=r"(f[3]) : "r"(a));
}
__device__ __forceinline__ void ldsm4t(u32* f, u32 a) {
    asm volatile("ldmatrix.sync.aligned.m8n8.x4.trans.shared.b16 {%0,%1,%2,%3}, [%4];"
                 : "=r"(f[0]), "=r"(f[1]), "=r"(f[2]), "=r"(f[3]) : "r"(a));
}
__device__ __forceinline__ void mma_f16(float* c, const u32* a, const u32* b) {
    asm volatile(
        "mma.sync.aligned.m16n8k16.row.col.f32.f16.f16.f32 "
        "{%0,%1,%2,%3}, {%4,%5,%6,%7}, {%8,%9}, {%0,%1,%2,%3};"
        : "+f"(c[0]), "+f"(c[1]), "+f"(c[2]), "+f"(c[3])
        : "r"(a[0]), "r"(a[1]), "r"(a[2]), "r"(a[3]), "r"(b[0]), "r"(b[1]));
}

// ---------------- smem layout ----------------
static constexpr u32 RS64  = 144;   // 64-wide fp16 tile row stride (bytes)
static constexpr u32 RS128 = 272;   // 128-wide tile row stride

static constexpr u32 OFF_X  = 0;        // 18432
static constexpr u32 OFF_W1 = 18432;    // 9216
static constexpr u32 OFF_W2 = 27648;    // 9216
static constexpr u32 OFF_AT = 36864;    // 34816
static constexpr u32 OFF_H2 = 71680;    // 18432
static constexpr u32 OFF_B1 = 90112;    // 256
static constexpr u32 OFF_B2 = 90368;    // 256
static constexpr u32 SMEM_BYTES = 90624;

static constexpr int I_PER_CTA = 8;

// =============== prep: A[b][k][j] -> At fp16 image ===============
__global__ void prep_At(const float* __restrict__ A)
{
    __shared__ float tile[32][33];
    const int b = blockIdx.z, k0 = blockIdx.x * 32, j0 = blockIdx.y * 32;
    const int tx = threadIdx.x & 31, ty = threadIdx.x >> 5;   // ty: 0..7

    const float* Ab = A + ((size_t)b * NN + k0) * NN + j0;
    #pragma unroll
    for (int s = 0; s < 4; ++s)
        tile[ty + 8 * s][tx] = Ab[(ty + 8 * s) * NN + tx];
    __syncthreads();

    const int j  = threadIdx.x >> 3;   // 0..31
    const int kq = threadIdx.x & 7;    // 4 k values each
    float v[4];
    #pragma unroll
    for (int s = 0; s < 4; ++s) v[s] = tile[kq * 4 + s][j];

    uint2 h = make_uint2(pack_h16(v[0], v[1]), pack_h16(v[2], v[3]));
    size_t off = (size_t)(j0 + j) * RS128 + (size_t)(k0 + kq * 4) * 2;
    *reinterpret_cast<uint2*>(&g_Ah[b][off]) = h;
}

// =============== main fused kernel ===============
__global__ __launch_bounds__(256, 2)
void crosssubg_mma_kernel(const float* __restrict__ X,
                          const float* __restrict__ W1,
                          const float* __restrict__ b1,
                          const float* __restrict__ W2,
                          const float* __restrict__ b2,
                          float* __restrict__ out)
{
    extern __shared__ __align__(1024) unsigned char smraw[];
    const u32 sb = smem_u32(smraw);

    const int ig   = blockIdx.x;            // i-group (0..15)
    const int b    = blockIdx.y;            // batch
    const int tid  = (int)threadIdx.x;
    const int wid  = tid >> 5;
    const int lane = tid & 31;
    const int row0 = wid * 16;              // G1/G2 m-rows
    const int wm   = wid >> 1, wn = wid & 1;
    const int j0   = wm * 32, d0 = wn * 32; // G3 warp tile origin

    // ---- one-time staging: W1, W2, At, biases ----
    {
        const float4* gW1 = (const float4*)W1;   // 1024 each
        const float4* gW2 = (const float4*)W2;
        #pragma unroll
        for (int it = 0; it < 8; ++it) {
            int t = tid + it * 256;              // 0..2047
            int sel = t >> 10;
            int r = t & 1023;
            float4 v = sel ? gW2[r] : gW1[r];
            int d = r >> 4, e0 = (r & 15) * 4;
            sts64(sb + (sel ? OFF_W2 : OFF_W1) + (u32)d * RS64 + (u32)e0 * 2,
                  pack_h16(v.x, v.y), pack_h16(v.z, v.w));
        }
        const uint4* gA = (const uint4*)&g_Ah[b][0];   // 2176 uint4
        #pragma unroll
        for (int it = 0; it < 9; ++it) {
            int t = tid + it * 256;
            if (t < 2176) {
                uint4 v = gA[t];
                sts128(sb + OFF_AT + (u32)t * 16, v.x, v.y, v.z, v.w);
            }
        }
        if (tid < 64)       sts32(sb + OFF_B1 + (u32)tid * 4, __float_as_uint(__ldg(&b1[tid])));
        else if (tid < 128) sts32(sb + OFF_B2 + (u32)(tid - 64) * 4, __float_as_uint(__ldg(&b2[tid - 64])));
    }
    __syncthreads();

    // precomputed fragment addresses
    const u32 aoffX = sb + OFF_X + ((u32)row0 + (u32)(lane & 15)) * RS64 + (u32)(lane >> 4) * 16;
    const u32 boffW = (u32)(lane & 15) * RS64 + (u32)(lane >> 4) * 16;
    const u32 aoffA = sb + OFF_AT + ((u32)j0 + (u32)(lane & 15)) * RS128 + (u32)(lane >> 4) * 16;
    const u32 boffH = sb + OFF_H2 + (u32)(lane & 15) * RS64 + (u32)d0 * 2 + (u32)(lane >> 4) * 16;

    for (int t8 = 0; t8 < I_PER_CTA; ++t8) {
        const size_t tile = (size_t)(b * NN + ig * I_PER_CTA + t8);

        // ---- stage X (fp16) ----
        {
            const float4* gX4 = (const float4*)(X + tile * (NN * DD));  // 2048 float4
            #pragma unroll
            for (int it = 0; it < 8; ++it) {
                int t = tid + it * 256;
                float4 v = gX4[t];
                int k = t >> 4, dq = (t & 15) * 4;
                sts64(sb + OFF_X + (u32)k * RS64 + (u32)dq * 2,
                      pack_h16(v.x, v.y), pack_h16(v.z, v.w));
            }
        }
        __syncthreads();   // bar1: X visible; G3(t-1) readers all past

        // ---- GEMM1: acc1 = X W1  (M=128 N=64 K=64) ----
        float acc1[8][4];
        #pragma unroll
        for (int n = 0; n < 8; ++n)
            #pragma unroll
            for (int q = 0; q < 4; ++q) acc1[n][q] = 0.0f;
        #pragma unroll
        for (int ks = 0; ks < 4; ++ks) {
            u32 fa[4];
            ldsm4(fa, aoffX + (u32)ks * 32);
            const u32 bb = sb + OFF_W1 + (u32)ks * 16 * RS64 + boffW;
            #pragma unroll
            for (int np = 0; np < 4; ++np) {
                u32 fb[4];
                ldsm4t(fb, bb + (u32)np * 32);
                mma_f16(acc1[2 * np],     fa, fb);
                mma_f16(acc1[2 * np + 1], fa, fb + 2);
            }
        }

        // ---- GEMM2: acc2 = relu(acc1 + b1) W2, A-fragments built in registers ----
        float acc2[8][4];
        #pragma unroll
        for (int n = 0; n < 8; ++n)
            #pragma unroll
            for (int q = 0; q < 4; ++q) acc2[n][q] = 0.0f;
        #pragma unroll
        for (int ks = 0; ks < 4; ++ks) {
            float bz0, bz1, bz2, bz3;
            lds64f(bz0, bz1, sb + OFF_B1 + (u32)(16 * ks + 2 * (lane & 3)) * 4);
            lds64f(bz2, bz3, sb + OFF_B1 + (u32)(16 * ks + 8 + 2 * (lane & 3)) * 4);
            u32 fa[4];
            fa[0] = pack_h16(fmaxf(acc1[2 * ks][0] + bz0, 0.f), fmaxf(acc1[2 * ks][1] + bz1, 0.f));
            fa[1] = pack_h16(fmaxf(acc1[2 * ks][2] + bz0, 0.f), fmaxf(acc1[2 * ks][3] + bz1, 0.f));
            fa[2] = pack_h16(fmaxf(acc1[2 * ks + 1][0] + bz2, 0.f), fmaxf(acc1[2 * ks + 1][1] + bz3, 0.f));
            fa[3] = pack_h16(fmaxf(acc1[2 * ks + 1][2] + bz2, 0.f), fmaxf(acc1[2 * ks + 1][3] + bz3, 0.f));
            const u32 bb = sb + OFF_W2 + (u32)ks * 16 * RS64 + boffW;
            #pragma unroll
            for (int np = 0; np < 4; ++np) {
                u32 fb[4];
                ldsm4t(fb, bb + (u32)np * 32);
                mma_f16(acc2[2 * np],     fa, fb);
                mma_f16(acc2[2 * np + 1], fa, fb + 2);
            }
        }

        // ---- h2 = relu(acc2 + b2) -> smem fp16 ----
        {
            const int r  = row0 + (lane >> 2);
            const int cb = 2 * (lane & 3);
            #pragma unroll
            for (int n0 = 0; n0 < 8; ++n0) {
                const int col = n0 * 8 + cb;
                float bz0, bz1;
                lds64f(bz0, bz1, sb + OFF_B2 + (u32)col * 4);
                float v0 = fmaxf(acc2[n0][0] + bz0, 0.f);
                float v1 = fmaxf(acc2[n0][1] + bz1, 0.f);
                float v2 = fmaxf(acc2[n0][2] + bz0, 0.f);
                float v3 = fmaxf(acc2[n0][3] + bz1, 0.f);
                const u32 a0 = sb + OFF_H2 + (u32)r * RS64 + (u32)col * 2;
                sts32(a0,             pack_h16(v0, v1));
                sts32(a0 + 8u * RS64, pack_h16(v2, v3));
            }
        }
        __syncthreads();   // bar2: h2 visible

        // ---- GEMM3: out[j][d] = sum_k At[j][k] h2[k][d]  (warp tile 32x32) ----
        float acc3[8][4];
        #pragma unroll
        for (int n = 0; n < 8; ++n)
            #pragma unroll
            for (int q = 0; q < 4; ++q) acc3[n][q] = 0.0f;
        #pragma unroll
        for (int ks = 0; ks < 8; ++ks) {
            u32 fa0[4], fa1[4], fb0[4], fb1[4];
            ldsm4(fa0, aoffA + (u32)ks * 32);
            ldsm4(fa1, aoffA + 16u * RS128 + (u32)ks * 32);
            const u32 bb = boffH + (u32)ks * 16 * RS64;
            ldsm4t(fb0, bb);
            ldsm4t(fb1, bb + 32);
            mma_f16(acc3[0], fa0, fb0); mma_f16(acc3[1], fa0, fb0 + 2);
            mma_f16(acc3[2], fa0, fb1); mma_f16(acc3[3], fa0, fb1 + 2);
            mma_f16(acc3[4], fa1, fb0); mma_f16(acc3[5], fa1, fb0 + 2);
            mma_f16(acc3[6], fa1, fb1); mma_f16(acc3[7], fa1, fb1 + 2);
        }

        // ---- store to global ----
        {
            float* gO = out + tile * (NN * DD);
            const int gr = lane >> 2, cb = 2 * (lane & 3);
            #pragma unroll
            for (int mb = 0; mb < 2; ++mb) {
                const int j = j0 + 16 * mb + gr;
                #pragma unroll
                for (int nb = 0; nb < 4; ++nb) {
                    const float* a = acc3[mb * 4 + nb];
                    const int col = d0 + 8 * nb + cb;
                    *(float2*)(gO + (size_t)j * DD + col)       = make_float2(a[0], a[1]);
                    *(float2*)(gO + (size_t)(j + 8) * DD + col) = make_float2(a[2], a[3]);
                }
            }
        }
        // next iteration's X staging is safe: everyone passed bar2 (G1/G2 done),
        // and G3 reads only At/h2.
    }
}

extern "C" void kernel_launch(void* const* d_in, const int* in_sizes, int n_in,
                              void* d_out, int out_size)
{
    const float *X = nullptr, *A = nullptr, *W1 = nullptr, *b1 = nullptr,
                *W2 = nullptr, *b2 = nullptr;
    for (int idx = 0; idx < n_in; ++idx) {
        const float* p = (const float*)d_in[idx];
        int s = in_sizes[idx];
        if      (s == NB * NN * NN * DD) X = p;
        else if (s == NB * NN * NN)      A = p;
        else if (s == DD * DD)           { if (!W1) W1 = p; else W2 = p; }
        else if (s == DD)                { if (!b1) b1 = p; else b2 = p; }
    }

    prep_At<<<dim3(4, 4, 32), 256>>>(A);

    cudaFuncSetAttribute(crosssubg_mma_kernel,
                         cudaFuncAttributeMaxDynamicSharedMemorySize, SMEM_BYTES);
    dim3 grid(NN / I_PER_CTA, NB);   // (16, 32)
    crosssubg_mma_kernel<<<grid, 256, SMEM_BYTES>>>(X, W1, b1, W2, b2, (float*)d_out);
}